// round 5
// baseline (speedup 1.0000x reference)
#include <cuda_runtime.h>
#include <cuda_fp16.h>

#define IH 256
#define IW 256
#define NPIX (IH * IW)          // 65536
#define NMAPS 88
#define SRC_ELEMS (NPIX * 3)    // 196608

#define QSTRIDE 132
#define QROWS 129
#define COPYSZ (QROWS * QSTRIDE)

// smem-resident rows
#define SROWS 151
#define RG_BYTES (SROWS * IW * 4)     // 154624
#define SMEM_BYTES (SROWS * IW * 6)   // 231936

#define NUNITS (NMAPS * NPIX / 2)     // 2,883,584 (2 pixels per unit)
#define PGRID 148
#define PBLOCK 1024

// ---- global scratch ----
struct __align__(32) Quad { uint4 a, b; };
__device__ Quad g_quads[4 * COPYSZ];        // baked-zero 2x2 fp16 quads (global gather path)
__device__ unsigned g_rg[NPIX];             // fp16 (r,g) per pixel
__device__ unsigned short g_b[NPIX];        // fp16 b per pixel

__device__ __forceinline__ void px_fetch(const float* __restrict__ s, int r, int c, __half* out) {
    if ((unsigned)r < IH && (unsigned)c < IW) {
        const float* p = s + (r * IW + c) * 3;
        out[0] = __float2half(p[0]);
        out[1] = __float2half(p[1]);
        out[2] = __float2half(p[2]);
        out[3] = __float2half(0.f);
    } else {
        out[0] = out[1] = out[2] = out[3] = __float2half(0.f);
    }
}

__global__ void pack_src_kernel(const float* __restrict__ src) {
    int t = blockIdx.x * blockDim.x + threadIdx.x;
    if (t < NPIX) {   // compact fp16 planes
        float r = src[t * 3 + 0], g = src[t * 3 + 1], b = src[t * 3 + 2];
        __half2 rg = __halves2half2(__float2half(r), __float2half(g));
        g_rg[t] = *reinterpret_cast<unsigned*>(&rg);
        __half hb = __float2half(b);
        g_b[t] = *reinterpret_cast<unsigned short*>(&hb);
    }
    if (t < 4 * COPYSZ) {   // parity quads
        int c   = t / COPYSZ;
        int rem = t % COPYSZ;
        int ky = rem / QSTRIDE;
        int kx = rem % QSTRIDE;
        int py = c >> 1, px = c & 1;
        int r0 = 2 * ky - py;
        int c0 = 2 * kx - px;
        __align__(32) __half h[16];
        px_fetch(src, r0,     c0,     h + 0);
        px_fetch(src, r0,     c0 + 1, h + 4);
        px_fetch(src, r0 + 1, c0,     h + 8);
        px_fetch(src, r0 + 1, c0 + 1, h + 12);
        g_quads[t] = *reinterpret_cast<Quad*>(h);
    }
}

__device__ __forceinline__ float2 h2f(float v) {
    __half2 h = *reinterpret_cast<__half2*>(&v);
    return __half22float2(h);
}

__global__ void __launch_bounds__(PBLOCK, 1) deform_kernel(
    const float* __restrict__ motions, float* __restrict__ out) {
    extern __shared__ char smem[];
    unsigned* srg = reinterpret_cast<unsigned*>(smem);
    __half*   sb  = reinterpret_cast<__half*>(smem + RG_BYTES);

    // fill smem image (rows 0..SROWS-1), coalesced from compact planes
    for (int i = threadIdx.x; i < SROWS * IW; i += PBLOCK) {
        srg[i] = g_rg[i];
        sb[i]  = *reinterpret_cast<const __half*>(&g_b[i]);
    }
    __syncthreads();

    const float4* m4 = reinterpret_cast<const float4*>(motions);
    float2* o2base = reinterpret_cast<float2*>(out);

    for (int u = blockIdx.x * PBLOCK + threadIdx.x; u < NUNITS; u += PGRID * PBLOCK) {
        float4 m = __ldcs(&m4[u]);
        float gx[2] = {m.x, m.z};
        float gy[2] = {m.y, m.w};
        float r[6];

#pragma unroll
        for (int s = 0; s < 2; s++) {
            float x = fmaf(gx[s], 128.f, 127.5f);   // [-0.5, 255.5)
            float y = fmaf(gy[s], 128.f, 127.5f);
            int xw = __float2int_rd(x);   // [-1, 255]
            int yn = __float2int_rd(y);   // [-1, 255]
            float fx = x - (float)xw;
            float fy = y - (float)yn;
            float wnw = (1.f - fy) * (1.f - fx);
            float wne = (1.f - fy) * fx;
            float wsw = fy * (1.f - fx);
            float wse = fy * fx;

            float R, G, B;
            if ((unsigned)yn <= (unsigned)(SROWS - 2) && (unsigned)xw <= (unsigned)(IW - 2)) {
                // fully in-bounds, smem path: 4x LDS.32 + 4x LDS.16
                int base = yn * IW + xw;
                float2 nw = __half22float2(*reinterpret_cast<__half2*>(&srg[base]));
                float2 ne = __half22float2(*reinterpret_cast<__half2*>(&srg[base + 1]));
                float2 sw = __half22float2(*reinterpret_cast<__half2*>(&srg[base + IW]));
                float2 se = __half22float2(*reinterpret_cast<__half2*>(&srg[base + IW + 1]));
                float bnw = __half2float(sb[base]);
                float bne = __half2float(sb[base + 1]);
                float bsw = __half2float(sb[base + IW]);
                float bse = __half2float(sb[base + IW + 1]);
                R = wnw * nw.x + wne * ne.x + wsw * sw.x + wse * se.x;
                G = wnw * nw.y + wne * ne.y + wsw * sw.y + wse * se.y;
                B = wnw * bnw  + wne * bne  + wsw * bsw  + wse * bse;
            } else {
                // global quad path (baked-zero borders handle OOB masks)
                int py = yn & 1, px = xw & 1;
                int ky = (yn + py) >> 1;
                int kx = (xw + px) >> 1;
                const Quad* qp = &g_quads[((py << 1) | px) * COPYSZ + ky * QSTRIDE + kx];
                float q0, q1, q2, q3, q4, q5, q6, q7;
                asm("ld.global.nc.v8.f32 {%0,%1,%2,%3,%4,%5,%6,%7}, [%8];"
                    : "=f"(q0), "=f"(q1), "=f"(q2), "=f"(q3),
                      "=f"(q4), "=f"(q5), "=f"(q6), "=f"(q7)
                    : "l"(qp));
                float2 nw = h2f(q0), ne = h2f(q2), sw = h2f(q4), se = h2f(q6);
                float bnw = h2f(q1).x, bne = h2f(q3).x, bsw = h2f(q5).x, bse = h2f(q7).x;
                R = wnw * nw.x + wne * ne.x + wsw * sw.x + wse * se.x;
                G = wnw * nw.y + wne * ne.y + wsw * sw.y + wse * se.y;
                B = wnw * bnw  + wne * bne  + wsw * bsw  + wse * bse;
            }
            r[s * 3 + 0] = R;
            r[s * 3 + 1] = G;
            r[s * 3 + 2] = B;
        }

        float2* o2 = o2base + (size_t)u * 3;
        __stcs(&o2[0], make_float2(r[0], r[1]));
        __stcs(&o2[1], make_float2(r[2], r[3]));
        __stcs(&o2[2], make_float2(r[4], r[5]));
    }
}

extern "C" void kernel_launch(void* const* d_in, const int* in_sizes, int n_in,
                              void* d_out, int out_size) {
    const float* source  = (const float*)d_in[0];
    const float* motions = (const float*)d_in[1];
    if (n_in >= 2 && in_sizes[0] != SRC_ELEMS) {
        source  = (const float*)d_in[1];
        motions = (const float*)d_in[0];
    }

    static_assert(SMEM_BYTES <= 232448, "smem over budget");
    cudaFuncSetAttribute(deform_kernel,
                         cudaFuncAttributeMaxDynamicSharedMemorySize, SMEM_BYTES);

    pack_src_kernel<<<(4 * COPYSZ + 255) / 256, 256>>>(source);
    deform_kernel<<<PGRID, PBLOCK, SMEM_BYTES>>>(motions, (float*)d_out);
}